// round 10
// baseline (speedup 1.0000x reference)
#include <cuda_runtime.h>
#include <cstdint>

#define B_    128
#define S_    512
#define H_    1024
#define MID_  512
#define E_    512
#define XE_   64
#define FEAT_ 576
#define H4_   4096
#define NBLK  148
#define NTHR  256

typedef unsigned long long u64;

// ---------------- persistent state + scratch (device globals; no allocs) ----------------
__device__ float g_h1[B_ * H_];
__device__ float g_c1[B_ * H_];
__device__ float g_h2[B_ * H_];
__device__ float g_c2[B_ * H_];
__device__ float g_zbb[B_ * MID_];
__device__ float g_mh[B_ * H_];
__device__ float g_z1p0[B_ * H4_];
__device__ float g_z1p1[B_ * H4_];
__device__ float g_x2[B_ * H_];
__device__ float g_mx2[B_ * H_];
__device__ float g_mh2[B_ * H_];
__device__ float g_z2[B_ * H4_];
__device__ float g_z2p0[B_ * H4_];
__device__ float g_z2p1[B_ * H4_];
__device__ float g_s[B_];
__device__ unsigned g_bar_count = 0;
__device__ unsigned g_bar_gen = 0;
// precomputed x-side results for ALL steps (input-only dependent)
__device__ float g_zba_all[S_ * B_ * MID_];   // 134 MB
__device__ float g_mx_all[S_ * B_ * H_];      // 268 MB
__device__ float g_z1_all[S_ * B_ * H4_];     // 1.07 GB

__device__ __forceinline__ float sigf(float x) { return 1.f / (1.f + expf(-x)); }
// L2-only loads for cross-block data (L1 persists within a persistent kernel -> stale otherwise)
__device__ __forceinline__ float4 cg4(const float* p) { return __ldcg((const float4*)p); }
__device__ __forceinline__ float  cg1(const float* p) { return __ldcg(p); }

// packed fp32x2 FMA (sm_100+): doubles fma-pipe flops per issue slot
#define FMA2(acc, a, b) asm("fma.rn.f32x2 %0, %1, %2, %0;" : "+l"(acc) : "l"(a), "l"(b))
#define UNPACK2(lo, hi, v) asm("mov.b64 {%0, %1}, %2;" : "=r"(lo), "=r"(hi) : "l"(v))

// ---------------- grid-wide barrier (all NBLK blocks co-resident by construction) ----------------
__device__ __forceinline__ void grid_barrier(unsigned& gen) {
    __syncthreads();
    if (threadIdx.x == 0) {
        __threadfence();
        unsigned arrived = atomicAdd(&g_bar_count, 1u) + 1u;
        if (arrived == (unsigned)NBLK) {
            g_bar_count = 0;
            __threadfence();
            atomicExch(&g_bar_gen, gen + 1u);
        } else {
            unsigned cur;
            do {
                __nanosleep(64);
                asm volatile("ld.global.cg.u32 %0, [%1];" : "=r"(cur) : "l"(&g_bar_gen));
            } while (cur == gen);
        }
        __threadfence();
    }
    __syncthreads();
    gen++;
}

// ---------------- A-tile loaders (M = 128 = full batch) ----------------
struct BufLoader {
    const float* A; int lda;
    __device__ __forceinline__ float4 ld(int m, int k) const {
        return cg4(A + (size_t)m * lda + k);
    }
};
struct MulLoader {  // A[m][k] = X[m][k] * Y[m][k], both [*, H_] (pre-offset by koff)
    const float* X; const float* Y;
    __device__ __forceinline__ float4 ld(int m, int k) const {
        float4 a = cg4(X + (size_t)m * H_ + k);
        float4 b = cg4(Y + (size_t)m * H_ + k);
        return make_float4(a.x * b.x, a.y * b.y, a.z * b.z, a.w * b.w);
    }
};
struct EmbLoader {  // gathered embedding row: [word_emb | extra_emb] (read-only tables, L1 ok)
    const float* we; const float* ee; const int* sw; const int* se;
    __device__ __forceinline__ float4 ld(int m, int k) const {
        if (k < E_) return *(const float4*)(we + (size_t)sw[m] * E_ + k);
        return *(const float4*)(ee + (size_t)se[m] * XE_ + (k - E_));
    }
};

typedef float SmA[32][128];   // A: [k][m]
typedef float SmW[32][128];   // W duplicated: Wd[k][2n] == Wd[k][2n+1] == W[n][k]

// ---------------- 128x64 tile GEMM: acc += A[128,K] @ W[64,K]^T ----------------
// 256 threads, BK=32, 8 rows x 4 cols per thread via row-pair fp32x2.
// W stored duplicated in smem -> {w,w} u64 pairs read directly, no PACK movs.
// Per kk: 4 LDS.128 + 16 FFMA2. One __syncthreads per 32-k chunk.
// Per-output k-order identical to the scalar loop -> bit-identical numerics.
template <class AL>
__device__ __forceinline__ void gemm_seg(u64 (&acc)[4][4], const AL& al,
                                         const float* __restrict__ W, int K,
                                         SmA* As, SmW* Wd) {
    const int tid = threadIdx.x;
    const int alm = tid >> 1;            // 0..127 : A load row
    const int alk = (tid & 1) << 4;      // 0,16   : A k-offset (4 float4)
    const int wlm = tid >> 2;            // 0..63  : W load row
    const int wlk = (tid & 3) << 3;      // 0,8,16,24 : W k-offset (2 float4)
    const int tm  = tid >> 4;            // 0..15 : rows 8tm..8tm+7
    const int tn  = tid & 15;            // 0..15 : cols 4tn..4tn+3
    float4 a0 = al.ld(alm, alk);
    float4 a1 = al.ld(alm, alk + 4);
    float4 a2 = al.ld(alm, alk + 8);
    float4 a3 = al.ld(alm, alk + 12);
    float4 w0 = *(const float4*)(W + (size_t)wlm * K + wlk);
    float4 w1 = *(const float4*)(W + (size_t)wlm * K + wlk + 4);
    const int nch = K >> 5;
    int buf = 0;
    for (int ch = 0; ch < nch; ch++) {
        As[buf][alk + 0][alm] = a0.x; As[buf][alk + 1][alm] = a0.y;
        As[buf][alk + 2][alm] = a0.z; As[buf][alk + 3][alm] = a0.w;
        As[buf][alk + 4][alm] = a1.x; As[buf][alk + 5][alm] = a1.y;
        As[buf][alk + 6][alm] = a1.z; As[buf][alk + 7][alm] = a1.w;
        As[buf][alk + 8][alm] = a2.x; As[buf][alk + 9][alm] = a2.y;
        As[buf][alk + 10][alm] = a2.z; As[buf][alk + 11][alm] = a2.w;
        As[buf][alk + 12][alm] = a3.x; As[buf][alk + 13][alm] = a3.y;
        As[buf][alk + 14][alm] = a3.z; As[buf][alk + 15][alm] = a3.w;
        *(float2*)&Wd[buf][wlk + 0][wlm << 1] = make_float2(w0.x, w0.x);
        *(float2*)&Wd[buf][wlk + 1][wlm << 1] = make_float2(w0.y, w0.y);
        *(float2*)&Wd[buf][wlk + 2][wlm << 1] = make_float2(w0.z, w0.z);
        *(float2*)&Wd[buf][wlk + 3][wlm << 1] = make_float2(w0.w, w0.w);
        *(float2*)&Wd[buf][wlk + 4][wlm << 1] = make_float2(w1.x, w1.x);
        *(float2*)&Wd[buf][wlk + 5][wlm << 1] = make_float2(w1.y, w1.y);
        *(float2*)&Wd[buf][wlk + 6][wlm << 1] = make_float2(w1.z, w1.z);
        *(float2*)&Wd[buf][wlk + 7][wlm << 1] = make_float2(w1.w, w1.w);
        __syncthreads();
        if (ch + 1 < nch) {   // prefetch next chunk; hidden behind compute
            const int kb = (ch + 1) << 5;
            a0 = al.ld(alm, kb + alk);
            a1 = al.ld(alm, kb + alk + 4);
            a2 = al.ld(alm, kb + alk + 8);
            a3 = al.ld(alm, kb + alk + 12);
            w0 = *(const float4*)(W + (size_t)wlm * K + kb + wlk);
            w1 = *(const float4*)(W + (size_t)wlm * K + kb + wlk + 4);
        }
#pragma unroll
        for (int kk = 0; kk < 32; kk++) {
            ulonglong2 ar0 = *(const ulonglong2*)&As[buf][kk][tm << 3];        // rowpairs 0,1
            ulonglong2 ar1 = *(const ulonglong2*)&As[buf][kk][(tm << 3) + 4];  // rowpairs 2,3
            ulonglong2 wda = *(const ulonglong2*)&Wd[buf][kk][tn << 3];        // {c0,c0},{c1,c1}
            ulonglong2 wdb = *(const ulonglong2*)&Wd[buf][kk][(tn << 3) + 4];  // {c2,c2},{c3,c3}
            FMA2(acc[0][0], ar0.x, wda.x); FMA2(acc[0][1], ar0.y, wda.x);
            FMA2(acc[0][2], ar1.x, wda.x); FMA2(acc[0][3], ar1.y, wda.x);
            FMA2(acc[1][0], ar0.x, wda.y); FMA2(acc[1][1], ar0.y, wda.y);
            FMA2(acc[1][2], ar1.x, wda.y); FMA2(acc[1][3], ar1.y, wda.y);
            FMA2(acc[2][0], ar0.x, wdb.x); FMA2(acc[2][1], ar0.y, wdb.x);
            FMA2(acc[2][2], ar1.x, wdb.x); FMA2(acc[2][3], ar1.y, wdb.x);
            FMA2(acc[3][0], ar0.x, wdb.y); FMA2(acc[3][1], ar0.y, wdb.y);
            FMA2(acc[3][2], ar1.x, wdb.y); FMA2(acc[3][3], ar1.y, wdb.y);
        }
        buf ^= 1;
    }
    __syncthreads();   // protect smem before reuse by next task/phase
}

__device__ __forceinline__ void store_tile(float* __restrict__ C, int ldc, int c0,
                                           u64 (&acc)[4][4], const float* __restrict__ bias) {
    const int tid = threadIdx.x;
    const int tm = tid >> 4, tn = tid & 15;
    float4 bv = make_float4(0.f, 0.f, 0.f, 0.f);
    if (bias) bv = *(const float4*)(bias + (tn << 2));
#pragma unroll
    for (int rp = 0; rp < 4; rp++) {
        unsigned l0, h0, l1, h1, l2, h2, l3, h3;
        UNPACK2(l0, h0, acc[0][rp]);
        UNPACK2(l1, h1, acc[1][rp]);
        UNPACK2(l2, h2, acc[2][rp]);
        UNPACK2(l3, h3, acc[3][rp]);
        const int r0 = (tm << 3) + (rp << 1);
        *(float4*)(C + (size_t)r0 * ldc + c0 + (tn << 2)) =
            make_float4(__uint_as_float(l0) + bv.x, __uint_as_float(l1) + bv.y,
                        __uint_as_float(l2) + bv.z, __uint_as_float(l3) + bv.w);
        *(float4*)(C + (size_t)(r0 + 1) * ldc + c0 + (tn << 2)) =
            make_float4(__uint_as_float(h0) + bv.x, __uint_as_float(h1) + bv.y,
                        __uint_as_float(h2) + bv.z, __uint_as_float(h3) + bv.w);
    }
}

// ---------------- the single persistent kernel ----------------
__global__ __launch_bounds__(NTHR) void enc_kernel(
    const int* __restrict__ enc, const int* __restrict__ encx,
    const float* __restrict__ we, const float* __restrict__ ee,
    const float* __restrict__ Wsi, const float* __restrict__ Wsh,
    const float* __restrict__ b_bd, const float* __restrict__ vs,
    const float* __restrict__ Wmx1, const float* __restrict__ Wmh1,
    const float* __restrict__ Wih1, const float* __restrict__ Whh1, const float* __restrict__ b1,
    const float* __restrict__ Wmx2, const float* __restrict__ Wmh2,
    const float* __restrict__ Wih2, const float* __restrict__ Whh2, const float* __restrict__ b2,
    float* __restrict__ out, float* __restrict__ out_h2,
    float* __restrict__ out_c2, float* __restrict__ out_flags) {
    __shared__ float As[2][32][128];
    __shared__ float Wd[2][32][128];
    __shared__ float red[NTHR];
    __shared__ int sw[128], se[128];
    const int tid = threadIdx.x;
    const int bid = blockIdx.x;
    unsigned gen = *((volatile unsigned*)&g_bar_gen);  // persists across graph replays

    // init: zero recurrent state AND the h-side scratch for t=0 (h1=0 -> zbb=0, mh=0)
    for (int i = bid * NTHR + tid; i < B_ * H_; i += NBLK * NTHR) {
        g_h1[i] = 0.f; g_c1[i] = 0.f; g_h2[i] = 0.f; g_c2[i] = 0.f; g_mh[i] = 0.f;
    }
    for (int i = bid * NTHR + tid; i < B_ * MID_; i += NBLK * NTHR) g_zbb[i] = 0.f;

    // ---- PRECOMPUTE: all x-side GEMMs for every step (no recurrent dependency).
    //      per step: zba (8 tiles, K=576), mx (16 tiles, K=576), z1pre (64 tiles, K=576)
    //      -> 88 tasks/step x 512 steps, perfectly parallel, no barriers.
    for (int task = bid; task < S_ * 88; task += NBLK) {
        const int t  = task / 88;
        const int ct = task - t * 88;
        if (tid < 128) {
            sw[tid] = enc[(size_t)tid * S_ + t];
            se[tid] = encx[(size_t)tid * S_ + t];
        }
        __syncthreads();
        u64 acc[4][4] = {};
        EmbLoader el{we, ee, sw, se};
        if (ct < 8) {
            const int c0 = ct << 6;
            gemm_seg(acc, el, Wsi + (size_t)c0 * FEAT_, FEAT_, As, Wd);
            store_tile(g_zba_all + (size_t)t * B_ * MID_, MID_, c0, acc, b_bd + c0);
        } else if (ct < 24) {
            const int c0 = (ct - 8) << 6;
            gemm_seg(acc, el, Wmx1 + (size_t)c0 * FEAT_, FEAT_, As, Wd);
            store_tile(g_mx_all + (size_t)t * B_ * H_, H_, c0, acc, nullptr);
        } else {
            const int c0 = (ct - 24) << 6;
            gemm_seg(acc, el, Wih1 + (size_t)c0 * FEAT_, FEAT_, As, Wd);
            store_tile(g_z1_all + (size_t)t * B_ * H4_, H4_, c0, acc, b1 + c0);
        }
    }
    grid_barrier(gen);

    for (int t = 0; t < S_; t++) {
        // ---- P2: z1p[half] = (mx_all[t]*mh)[:,koff:+512] @ Whh1[:,koff:+512]^T  (128 tasks, K=512)
        //      mh for this step was produced in PHASE_A of step t-1 (zeros at t=0).
        if (bid < 128) {
            const int r = bid;
            const int c0 = (r >> 1) << 6;
            const int koff = (r & 1) << 9;
            u64 acc[4][4] = {};
            MulLoader ml{g_mx_all + (size_t)t * B_ * H_ + koff, g_mh + koff};
            gemm_seg(acc, ml, Whh1 + (size_t)c0 * H_ + koff, 512, As, Wd);
            store_tile((r & 1) ? g_z1p1 : g_z1p0, H4_, c0, acc, nullptr);
        }
        grid_barrier(gen);

        // ---- P3: boundary s, cell1 gates, h1/c1 reset, x2   (128 blocks = 128 batches)
        if (bid < B_) {
            const int b = bid;
            const float* zba = g_zba_all + (size_t)t * B_ * MID_;
            float v = (cg1(&zba[(size_t)b * MID_ + tid]) + cg1(&g_zbb[(size_t)b * MID_ + tid])) * vs[tid] +
                      (cg1(&zba[(size_t)b * MID_ + 256 + tid]) + cg1(&g_zbb[(size_t)b * MID_ + 256 + tid])) * vs[256 + tid];
            red[tid] = v;
            __syncthreads();
            for (int off = 128; off > 0; off >>= 1) {
                if (tid < off) red[tid] += red[tid + off];
                __syncthreads();
            }
            const float s = (red[0] > 0.f) ? 1.f : 0.f;  // sigmoid(x)>0.5 <=> x>0 (exact)
            if (tid == 0) g_s[b] = s;
            {
                const int j = tid << 2;   // 256 threads x float4 == H_
                const size_t o = (size_t)b * H_ + j;
                const float* z1 = g_z1_all + (size_t)t * B_ * H4_;
                const size_t z = (size_t)b * H4_ + j;
                float4 zi = cg4(&z1[z]);            float4 pi0 = cg4(&g_z1p0[z]);            float4 pi1 = cg4(&g_z1p1[z]);
                float4 zf = cg4(&z1[z + H_]);       float4 pf0 = cg4(&g_z1p0[z + H_]);       float4 pf1 = cg4(&g_z1p1[z + H_]);
                float4 zg = cg4(&z1[z + 2 * H_]);   float4 pg0 = cg4(&g_z1p0[z + 2 * H_]);   float4 pg1 = cg4(&g_z1p1[z + 2 * H_]);
                float4 zo = cg4(&z1[z + 3 * H_]);   float4 po0 = cg4(&g_z1p0[z + 3 * H_]);   float4 po1 = cg4(&g_z1p1[z + 3 * H_]);
                float4 c1v = *(const float4*)&g_c1[o];   // same-block r/w across steps: L1 valid
                float xi[4] = {zi.x + pi0.x + pi1.x, zi.y + pi0.y + pi1.y, zi.z + pi0.z + pi1.z, zi.w + pi0.w + pi1.w};
                float xf[4] = {zf.x + pf0.x + pf1.x, zf.y + pf0.y + pf1.y, zf.z + pf0.z + pf1.z, zf.w + pf0.w + pf1.w};
                float xg[4] = {zg.x + pg0.x + pg1.x, zg.y + pg0.y + pg1.y, zg.z + pg0.z + pg1.z, zg.w + pg0.w + pg1.w};
                float xo[4] = {zo.x + po0.x + po1.x, zo.y + po0.y + po1.y, zo.z + po0.z + po1.z, zo.w + po0.w + po1.w};
                float cv[4] = {c1v.x, c1v.y, c1v.z, c1v.w};
                float x2v[4], h1v[4], c1n[4];
#pragma unroll
                for (int q = 0; q < 4; q++) {
                    float cn = sigf(xf[q]) * cv[q] + sigf(xi[q]) * tanhf(xg[q]);
                    float hn = sigf(xo[q]) * tanhf(cn);
                    x2v[q] = hn * s;
                    h1v[q] = hn * (1.f - s);
                    c1n[q] = cn * (1.f - s);
                }
                *(float4*)&g_x2[o] = make_float4(x2v[0], x2v[1], x2v[2], x2v[3]);
                *(float4*)&g_h1[o] = make_float4(h1v[0], h1v[1], h1v[2], h1v[3]);
                *(float4*)&g_c1[o] = make_float4(c1n[0], c1n[1], c1n[2], c1n[3]);
            }
        }
        grid_barrier(gen);

        const float s0 = cg1(&g_s[0]);  // uniform after barrier -> uniform control flow

        // ---- PHASE_A: blocks 0..95: P4(t) when flag; blocks 96..119: P1'(t+1) = zbb/mh
        //      from the just-updated h1 (always runs; consumed by P2/P3 of step t+1).
        if (s0 > 0.5f && bid < 96) {
            const int ct = bid;
            u64 acc[4][4] = {};
            if (ct < 16) {
                const int c0 = ct << 6;
                BufLoader bl{g_x2, H_};
                gemm_seg(acc, bl, Wmx2 + (size_t)c0 * H_, H_, As, Wd);
                store_tile(g_mx2, H_, c0, acc, nullptr);
            } else if (ct < 32) {
                const int c0 = (ct - 16) << 6;
                BufLoader bl{g_h2, H_};
                gemm_seg(acc, bl, Wmh2 + (size_t)c0 * H_, H_, As, Wd);
                store_tile(g_mh2, H_, c0, acc, nullptr);
            } else {
                const int c0 = (ct - 32) << 6;
                BufLoader bl{g_x2, H_};
                gemm_seg(acc, bl, Wih2 + (size_t)c0 * H_, H_, As, Wd);
                store_tile(g_z2, H4_, c0, acc, b2 + c0);
            }
        } else if (bid >= 96 && bid < 120) {
            const int p = bid - 96;
            u64 acc[4][4] = {};
            BufLoader bl{g_h1, H_};
            if (p < 8) {
                const int c0 = p << 6;
                gemm_seg(acc, bl, Wsh + (size_t)c0 * H_, H_, As, Wd);
                store_tile(g_zbb, MID_, c0, acc, nullptr);
            } else {
                const int c0 = (p - 8) << 6;
                gemm_seg(acc, bl, Wmh1 + (size_t)c0 * H_, H_, As, Wd);
                store_tile(g_mh, H_, c0, acc, nullptr);
            }
        }
        grid_barrier(gen);

        if (s0 > 0.5f) {
            // ---- P5: z2p[half] = (mx2*mh2)[:,koff:+512] @ Whh2[:,koff:+512]^T  (128 tasks, K=512)
            if (bid < 128) {
                const int r = bid;
                const int c0 = (r >> 1) << 6;
                const int koff = (r & 1) << 9;
                u64 acc[4][4] = {};
                MulLoader ml{g_mx2 + koff, g_mh2 + koff};
                gemm_seg(acc, ml, Whh2 + (size_t)c0 * H_ + koff, 512, As, Wd);
                store_tile((r & 1) ? g_z2p1 : g_z2p0, H4_, c0, acc, nullptr);
            }
            grid_barrier(gen);
        }

        // ---- P6: cell2 gates under scalar flag, write outs[:,t,:] + flags[t]
        // No trailing barrier: P6 writes {h2,c2,out}; next-step P2 touches disjoint buffers,
        // and the P2/P3-end barriers order P6 before any PHASE_A(t+1) read/write.
        if (bid < B_) {
            const int b = bid;
            const bool upd = s0 > 0.5f;
            const int j = tid << 2;
            const size_t o = (size_t)b * H_ + j;
            float4 h2v = *(const float4*)&g_h2[o];   // same-block r/w: L1 valid
            if (upd) {
                const size_t z = (size_t)b * H4_ + j;
                float4 zi = cg4(&g_z2[z]);            float4 pi0 = cg4(&g_z2p0[z]);            float4 pi1 = cg4(&g_z2p1[z]);
                float4 zf = cg4(&g_z2[z + H_]);       float4 pf0 = cg4(&g_z2p0[z + H_]);       float4 pf1 = cg4(&g_z2p1[z + H_]);
                float4 zg = cg4(&g_z2[z + 2 * H_]);   float4 pg0 = cg4(&g_z2p0[z + 2 * H_]);   float4 pg1 = cg4(&g_z2p1[z + 2 * H_]);
                float4 zo = cg4(&g_z2[z + 3 * H_]);   float4 po0 = cg4(&g_z2p0[z + 3 * H_]);   float4 po1 = cg4(&g_z2p1[z + 3 * H_]);
                float4 c2v = *(const float4*)&g_c2[o];
                float xi[4] = {zi.x + pi0.x + pi1.x, zi.y + pi0.y + pi1.y, zi.z + pi0.z + pi1.z, zi.w + pi0.w + pi1.w};
                float xf[4] = {zf.x + pf0.x + pf1.x, zf.y + pf0.y + pf1.y, zf.z + pf0.z + pf1.z, zf.w + pf0.w + pf1.w};
                float xg[4] = {zg.x + pg0.x + pg1.x, zg.y + pg0.y + pg1.y, zg.z + pg0.z + pg1.z, zg.w + pg0.w + pg1.w};
                float xo[4] = {zo.x + po0.x + po1.x, zo.y + po0.y + po1.y, zo.z + po0.z + po1.z, zo.w + po0.w + po1.w};
                float cv[4] = {c2v.x, c2v.y, c2v.z, c2v.w};
                float hn[4], cn[4];
#pragma unroll
                for (int q = 0; q < 4; q++) {
                    cn[q] = sigf(xf[q]) * cv[q] + sigf(xi[q]) * tanhf(xg[q]);
                    hn[q] = sigf(xo[q]) * tanhf(cn[q]);
                }
                h2v = make_float4(hn[0], hn[1], hn[2], hn[3]);
                *(float4*)&g_h2[o] = h2v;
                *(float4*)&g_c2[o] = make_float4(cn[0], cn[1], cn[2], cn[3]);
            }
            *(float4*)&out[(size_t)b * S_ * H_ + (size_t)t * H_ + j] = h2v;
            if (b == 0 && tid == 0 && out_flags) out_flags[t] = s0;
        }
    }

    // order all P6 writes before the cross-block final state copy
    grid_barrier(gen);
    if (out_h2) {
        for (int i = bid * NTHR + tid; i < B_ * H_; i += NBLK * NTHR) {
            out_h2[i] = cg1(&g_h2[i]);
            out_c2[i] = cg1(&g_c2[i]);
        }
    }
}

// ---------------- host: exactly ONE graph node ----------------
extern "C" void kernel_launch(void* const* d_in, const int* in_sizes, int n_in,
                              void* d_out, int out_size) {
    const int*   enc   = (const int*)d_in[0];
    const int*   encx  = (const int*)d_in[1];
    const float* we    = (const float*)d_in[2];
    const float* ee    = (const float*)d_in[3];
    const float* Wsi   = (const float*)d_in[4];
    const float* Wsh   = (const float*)d_in[5];
    const float* b_bd  = (const float*)d_in[6];
    const float* vs    = (const float*)d_in[7];
    const float* Wmx1  = (const float*)d_in[8];
    const float* Wmh1  = (const float*)d_in[9];
    const float* Wih1  = (const float*)d_in[10];
    const float* Whh1  = (const float*)d_in[11];
    const float* b1    = (const float*)d_in[12];
    const float* Wmx2  = (const float*)d_in[13];
    const float* Wmh2  = (const float*)d_in[14];
    const float* Wih2  = (const float*)d_in[15];
    const float* Whh2  = (const float*)d_in[16];
    const float* b2    = (const float*)d_in[17];
    float* out = (float*)d_out;

    const size_t outs_elems  = (size_t)B_ * S_ * H_;
    const size_t state_elems = (size_t)B_ * H_;
    float* out_h2 = nullptr;
    float* out_c2 = nullptr;
    float* out_flags = nullptr;
    if ((size_t)out_size >= outs_elems + 2 * state_elems + S_) {
        out_h2 = out + outs_elems;
        out_c2 = out_h2 + state_elems;
        out_flags = out_c2 + state_elems;
    }

    enc_kernel<<<NBLK, NTHR>>>(enc, encx, we, ee, Wsi, Wsh, b_bd, vs,
                               Wmx1, Wmh1, Wih1, Whh1, b1,
                               Wmx2, Wmh2, Wih2, Whh2, b2,
                               out, out_h2, out_c2, out_flags);
    (void)in_sizes; (void)n_in;
}

// round 11
// speedup vs baseline: 1.4795x; 1.4795x over previous
#include <cuda_runtime.h>
#include <cstdint>

#define B_    128
#define S_    512
#define H_    1024
#define MID_  512
#define E_    512
#define XE_   64
#define FEAT_ 576
#define H4_   4096
#define NBLK  148
#define NTHR  256

typedef unsigned long long u64;

// ---------------- persistent state + scratch (device globals; no allocs) ----------------
__device__ float g_h1[B_ * H_];
__device__ float g_c1[B_ * H_];
__device__ float g_h2[B_ * H_];
__device__ float g_c2[B_ * H_];
__device__ float g_zbb[B_ * MID_];
__device__ float g_mh[B_ * H_];
__device__ float g_z1p0[B_ * H4_];
__device__ float g_z1p1[B_ * H4_];
__device__ float g_x2[B_ * H_];
__device__ float g_mx2[B_ * H_];
__device__ float g_mh2[B_ * H_];
__device__ float g_z2[B_ * H4_];
__device__ float g_z2p0[B_ * H4_];
__device__ float g_z2p1[B_ * H4_];
__device__ float g_s[B_];
__device__ unsigned g_bar_count = 0;
__device__ unsigned g_bar_gen = 0;
// precomputed x-side results for ALL steps (input-only dependent)
__device__ float g_zba_all[S_ * B_ * MID_];   // 134 MB
__device__ float g_mx_all[S_ * B_ * H_];      // 268 MB
__device__ float g_z1_all[S_ * B_ * H4_];     // 1.07 GB

__device__ __forceinline__ float sigf(float x) { return 1.f / (1.f + expf(-x)); }
// L2-only loads for cross-block data (L1 persists within a persistent kernel -> stale otherwise)
__device__ __forceinline__ float4 cg4(const float* p) { return __ldcg((const float4*)p); }
__device__ __forceinline__ float  cg1(const float* p) { return __ldcg(p); }

// packed fp32x2 FMA (sm_100+): doubles fma-pipe flops per issue slot
#define FMA2(acc, a, b) asm("fma.rn.f32x2 %0, %1, %2, %0;" : "+l"(acc) : "l"(a), "l"(b))
#define PACK2(d, f)     asm("mov.b64 %0, {%1, %1};" : "=l"(d) : "r"(__float_as_uint(f)))
#define UNPACK2(lo, hi, v) asm("mov.b64 {%0, %1}, %2;" : "=r"(lo), "=r"(hi) : "l"(v))

// ---------------- grid-wide barrier (all NBLK blocks co-resident by construction) ----------------
__device__ __forceinline__ void grid_barrier(unsigned& gen) {
    __syncthreads();
    if (threadIdx.x == 0) {
        __threadfence();
        unsigned arrived = atomicAdd(&g_bar_count, 1u) + 1u;
        if (arrived == (unsigned)NBLK) {
            g_bar_count = 0;
            __threadfence();
            atomicExch(&g_bar_gen, gen + 1u);
        } else {
            unsigned cur;
            do {
                __nanosleep(64);
                asm volatile("ld.global.cg.u32 %0, [%1];" : "=r"(cur) : "l"(&g_bar_gen));
            } while (cur == gen);
        }
        __threadfence();
    }
    __syncthreads();
    gen++;
}

// ---------------- A-tile loaders (M = 128 = full batch) ----------------
struct BufLoader {
    const float* A; int lda;
    __device__ __forceinline__ float4 ld(int m, int k) const {
        return cg4(A + (size_t)m * lda + k);
    }
};
struct MulLoader {  // A[m][k] = X[m][k] * Y[m][k], both [*, H_] (pre-offset by koff)
    const float* X; const float* Y;
    __device__ __forceinline__ float4 ld(int m, int k) const {
        float4 a = cg4(X + (size_t)m * H_ + k);
        float4 b = cg4(Y + (size_t)m * H_ + k);
        return make_float4(a.x * b.x, a.y * b.y, a.z * b.z, a.w * b.w);
    }
};
struct EmbLoader {  // gathered embedding row: [word_emb | extra_emb] (read-only tables, L1 ok)
    const float* we; const float* ee; const int* sw; const int* se;
    __device__ __forceinline__ float4 ld(int m, int k) const {
        if (k < E_) return *(const float4*)(we + (size_t)sw[m] * E_ + k);
        return *(const float4*)(ee + (size_t)se[m] * XE_ + (k - E_));
    }
};

typedef float SmA[16][128];
typedef float SmW[16][64];

// ---------------- 128x64 tile GEMM: acc += A[128,K] @ W[64,K]^T ----------------
// 256 threads, BK=16, 8 rows x 4 cols per thread via row-pair fp32x2.
// Inner loop: explicit 1-deep register pipeline (load kk+1 before kk's FMAs) and
// 4 independent wp packs (no serial register reuse) -> fewer LDS-latency stalls.
// Per-output k-order identical to the scalar loop -> bit-identical numerics.
template <class AL>
__device__ __forceinline__ void gemm_seg(u64 (&acc)[4][4], const AL& al,
                                         const float* __restrict__ W, int K,
                                         SmA* As, SmW* Ws) {
    const int tid = threadIdx.x;
    const int lm  = tid >> 2;          // 0..63 : load row (and +64)
    const int lk  = (tid & 3) << 2;    // 0,4,8,12 : load k offset
    const int tm  = tid >> 4;          // 0..15 : rows 8tm..8tm+7
    const int tn  = tid & 15;          // 0..15 : cols 4tn..4tn+3
    float4 a0 = al.ld(lm, lk);
    float4 a1 = al.ld(lm + 64, lk);
    float4 w  = *(const float4*)(W + (size_t)lm * K + lk);
    const int nch = K >> 4;
    int buf = 0;
    for (int ch = 0; ch < nch; ch++) {
        As[buf][lk + 0][lm] = a0.x; As[buf][lk + 1][lm] = a0.y;
        As[buf][lk + 2][lm] = a0.z; As[buf][lk + 3][lm] = a0.w;
        As[buf][lk + 0][lm + 64] = a1.x; As[buf][lk + 1][lm + 64] = a1.y;
        As[buf][lk + 2][lm + 64] = a1.z; As[buf][lk + 3][lm + 64] = a1.w;
        Ws[buf][lk + 0][lm] = w.x; Ws[buf][lk + 1][lm] = w.y;
        Ws[buf][lk + 2][lm] = w.z; Ws[buf][lk + 3][lm] = w.w;
        __syncthreads();
        if (ch + 1 < nch) {   // prefetch next chunk from global; hidden behind compute
            a0 = al.ld(lm, ((ch + 1) << 4) + lk);
            a1 = al.ld(lm + 64, ((ch + 1) << 4) + lk);
            w  = *(const float4*)(W + (size_t)lm * K + ((ch + 1) << 4) + lk);
        }
        // software-pipelined inner loop over kk (full unroll): smem loads run 1 iter ahead
        ulonglong2 ar0 = *(const ulonglong2*)&As[buf][0][tm << 3];
        ulonglong2 ar1 = *(const ulonglong2*)&As[buf][0][(tm << 3) + 4];
        float4     wv  = *(const float4*)&Ws[buf][0][tn << 2];
#pragma unroll
        for (int kk = 0; kk < 16; kk++) {
            ulonglong2 nar0, nar1; float4 nwv;
            if (kk < 15) {
                nar0 = *(const ulonglong2*)&As[buf][kk + 1][tm << 3];
                nar1 = *(const ulonglong2*)&As[buf][kk + 1][(tm << 3) + 4];
                nwv  = *(const float4*)&Ws[buf][kk + 1][tn << 2];
            }
            u64 wp0, wp1, wp2, wp3;
            PACK2(wp0, wv.x); PACK2(wp1, wv.y); PACK2(wp2, wv.z); PACK2(wp3, wv.w);
            FMA2(acc[0][0], ar0.x, wp0); FMA2(acc[0][1], ar0.y, wp0);
            FMA2(acc[0][2], ar1.x, wp0); FMA2(acc[0][3], ar1.y, wp0);
            FMA2(acc[1][0], ar0.x, wp1); FMA2(acc[1][1], ar0.y, wp1);
            FMA2(acc[1][2], ar1.x, wp1); FMA2(acc[1][3], ar1.y, wp1);
            FMA2(acc[2][0], ar0.x, wp2); FMA2(acc[2][1], ar0.y, wp2);
            FMA2(acc[2][2], ar1.x, wp2); FMA2(acc[2][3], ar1.y, wp2);
            FMA2(acc[3][0], ar0.x, wp3); FMA2(acc[3][1], ar0.y, wp3);
            FMA2(acc[3][2], ar1.x, wp3); FMA2(acc[3][3], ar1.y, wp3);
            if (kk < 15) { ar0 = nar0; ar1 = nar1; wv = nwv; }
        }
        buf ^= 1;
    }
    __syncthreads();   // protect smem before reuse by next task/phase
}

__device__ __forceinline__ void store_tile(float* __restrict__ C, int ldc, int c0,
                                           u64 (&acc)[4][4], const float* __restrict__ bias) {
    const int tid = threadIdx.x;
    const int tm = tid >> 4, tn = tid & 15;
    float4 bv = make_float4(0.f, 0.f, 0.f, 0.f);
    if (bias) bv = *(const float4*)(bias + (tn << 2));
#pragma unroll
    for (int rp = 0; rp < 4; rp++) {
        unsigned l0, h0, l1, h1, l2, h2, l3, h3;
        UNPACK2(l0, h0, acc[0][rp]);
        UNPACK2(l1, h1, acc[1][rp]);
        UNPACK2(l2, h2, acc[2][rp]);
        UNPACK2(l3, h3, acc[3][rp]);
        const int r0 = (tm << 3) + (rp << 1);
        *(float4*)(C + (size_t)r0 * ldc + c0 + (tn << 2)) =
            make_float4(__uint_as_float(l0) + bv.x, __uint_as_float(l1) + bv.y,
                        __uint_as_float(l2) + bv.z, __uint_as_float(l3) + bv.w);
        *(float4*)(C + (size_t)(r0 + 1) * ldc + c0 + (tn << 2)) =
            make_float4(__uint_as_float(h0) + bv.x, __uint_as_float(h1) + bv.y,
                        __uint_as_float(h2) + bv.z, __uint_as_float(h3) + bv.w);
    }
}

// ---------------- the single persistent kernel ----------------
__global__ __launch_bounds__(NTHR) void enc_kernel(
    const int* __restrict__ enc, const int* __restrict__ encx,
    const float* __restrict__ we, const float* __restrict__ ee,
    const float* __restrict__ Wsi, const float* __restrict__ Wsh,
    const float* __restrict__ b_bd, const float* __restrict__ vs,
    const float* __restrict__ Wmx1, const float* __restrict__ Wmh1,
    const float* __restrict__ Wih1, const float* __restrict__ Whh1, const float* __restrict__ b1,
    const float* __restrict__ Wmx2, const float* __restrict__ Wmh2,
    const float* __restrict__ Wih2, const float* __restrict__ Whh2, const float* __restrict__ b2,
    float* __restrict__ out, float* __restrict__ out_h2,
    float* __restrict__ out_c2, float* __restrict__ out_flags) {
    __shared__ float As[2][16][128];
    __shared__ float Ws[2][16][64];
    __shared__ float red[NTHR];
    __shared__ int sw[128], se[128];
    const int tid = threadIdx.x;
    const int bid = blockIdx.x;
    unsigned gen = *((volatile unsigned*)&g_bar_gen);  // persists across graph replays

    // init: zero recurrent state AND the h-side scratch for t=0 (h1=0 -> zbb=0, mh=0)
    for (int i = bid * NTHR + tid; i < B_ * H_; i += NBLK * NTHR) {
        g_h1[i] = 0.f; g_c1[i] = 0.f; g_h2[i] = 0.f; g_c2[i] = 0.f; g_mh[i] = 0.f;
    }
    for (int i = bid * NTHR + tid; i < B_ * MID_; i += NBLK * NTHR) g_zbb[i] = 0.f;

    // ---- PRECOMPUTE: all x-side GEMMs for every step (no recurrent dependency).
    //      per step: zba (8 tiles, K=576), mx (16 tiles, K=576), z1pre (64 tiles, K=576)
    //      -> 88 tasks/step x 512 steps, perfectly parallel, no barriers.
    for (int task = bid; task < S_ * 88; task += NBLK) {
        const int t  = task / 88;
        const int ct = task - t * 88;
        if (tid < 128) {
            sw[tid] = enc[(size_t)tid * S_ + t];
            se[tid] = encx[(size_t)tid * S_ + t];
        }
        __syncthreads();
        u64 acc[4][4] = {};
        EmbLoader el{we, ee, sw, se};
        if (ct < 8) {
            const int c0 = ct << 6;
            gemm_seg(acc, el, Wsi + (size_t)c0 * FEAT_, FEAT_, As, Ws);
            store_tile(g_zba_all + (size_t)t * B_ * MID_, MID_, c0, acc, b_bd + c0);
        } else if (ct < 24) {
            const int c0 = (ct - 8) << 6;
            gemm_seg(acc, el, Wmx1 + (size_t)c0 * FEAT_, FEAT_, As, Ws);
            store_tile(g_mx_all + (size_t)t * B_ * H_, H_, c0, acc, nullptr);
        } else {
            const int c0 = (ct - 24) << 6;
            gemm_seg(acc, el, Wih1 + (size_t)c0 * FEAT_, FEAT_, As, Ws);
            store_tile(g_z1_all + (size_t)t * B_ * H4_, H4_, c0, acc, b1 + c0);
        }
    }
    grid_barrier(gen);

    for (int t = 0; t < S_; t++) {
        // ---- P2: z1p[half] = (mx_all[t]*mh)[:,koff:+512] @ Whh1[:,koff:+512]^T  (128 tasks, K=512)
        //      mh for this step was produced in PHASE_A of step t-1 (zeros at t=0).
        if (bid < 128) {
            const int r = bid;
            const int c0 = (r >> 1) << 6;
            const int koff = (r & 1) << 9;
            u64 acc[4][4] = {};
            MulLoader ml{g_mx_all + (size_t)t * B_ * H_ + koff, g_mh + koff};
            gemm_seg(acc, ml, Whh1 + (size_t)c0 * H_ + koff, 512, As, Ws);
            store_tile((r & 1) ? g_z1p1 : g_z1p0, H4_, c0, acc, nullptr);
        }
        grid_barrier(gen);

        // ---- P3: boundary s, cell1 gates, h1/c1 reset, x2   (128 blocks = 128 batches)
        if (bid < B_) {
            const int b = bid;
            const float* zba = g_zba_all + (size_t)t * B_ * MID_;
            float v = (cg1(&zba[(size_t)b * MID_ + tid]) + cg1(&g_zbb[(size_t)b * MID_ + tid])) * vs[tid] +
                      (cg1(&zba[(size_t)b * MID_ + 256 + tid]) + cg1(&g_zbb[(size_t)b * MID_ + 256 + tid])) * vs[256 + tid];
            red[tid] = v;
            __syncthreads();
            for (int off = 128; off > 0; off >>= 1) {
                if (tid < off) red[tid] += red[tid + off];
                __syncthreads();
            }
            const float s = (red[0] > 0.f) ? 1.f : 0.f;  // sigmoid(x)>0.5 <=> x>0 (exact)
            if (tid == 0) g_s[b] = s;
            {
                const int j = tid << 2;   // 256 threads x float4 == H_
                const size_t o = (size_t)b * H_ + j;
                const float* z1 = g_z1_all + (size_t)t * B_ * H4_;
                const size_t z = (size_t)b * H4_ + j;
                float4 zi = cg4(&z1[z]);            float4 pi0 = cg4(&g_z1p0[z]);            float4 pi1 = cg4(&g_z1p1[z]);
                float4 zf = cg4(&z1[z + H_]);       float4 pf0 = cg4(&g_z1p0[z + H_]);       float4 pf1 = cg4(&g_z1p1[z + H_]);
                float4 zg = cg4(&z1[z + 2 * H_]);   float4 pg0 = cg4(&g_z1p0[z + 2 * H_]);   float4 pg1 = cg4(&g_z1p1[z + 2 * H_]);
                float4 zo = cg4(&z1[z + 3 * H_]);   float4 po0 = cg4(&g_z1p0[z + 3 * H_]);   float4 po1 = cg4(&g_z1p1[z + 3 * H_]);
                float4 c1v = *(const float4*)&g_c1[o];   // same-block r/w across steps: L1 valid
                float xi[4] = {zi.x + pi0.x + pi1.x, zi.y + pi0.y + pi1.y, zi.z + pi0.z + pi1.z, zi.w + pi0.w + pi1.w};
                float xf[4] = {zf.x + pf0.x + pf1.x, zf.y + pf0.y + pf1.y, zf.z + pf0.z + pf1.z, zf.w + pf0.w + pf1.w};
                float xg[4] = {zg.x + pg0.x + pg1.x, zg.y + pg0.y + pg1.y, zg.z + pg0.z + pg1.z, zg.w + pg0.w + pg1.w};
                float xo[4] = {zo.x + po0.x + po1.x, zo.y + po0.y + po1.y, zo.z + po0.z + po1.z, zo.w + po0.w + po1.w};
                float cv[4] = {c1v.x, c1v.y, c1v.z, c1v.w};
                float x2v[4], h1v[4], c1n[4];
#pragma unroll
                for (int q = 0; q < 4; q++) {
                    float cn = sigf(xf[q]) * cv[q] + sigf(xi[q]) * tanhf(xg[q]);
                    float hn = sigf(xo[q]) * tanhf(cn);
                    x2v[q] = hn * s;
                    h1v[q] = hn * (1.f - s);
                    c1n[q] = cn * (1.f - s);
                }
                *(float4*)&g_x2[o] = make_float4(x2v[0], x2v[1], x2v[2], x2v[3]);
                *(float4*)&g_h1[o] = make_float4(h1v[0], h1v[1], h1v[2], h1v[3]);
                *(float4*)&g_c1[o] = make_float4(c1n[0], c1n[1], c1n[2], c1n[3]);
            }
        }
        grid_barrier(gen);

        const float s0 = cg1(&g_s[0]);  // uniform after barrier -> uniform control flow

        // ---- PHASE_A: blocks 0..95: P4(t) when flag; blocks 96..119: P1'(t+1) = zbb/mh
        //      from the just-updated h1 (always runs; consumed by P2/P3 of step t+1).
        if (s0 > 0.5f && bid < 96) {
            const int ct = bid;
            u64 acc[4][4] = {};
            if (ct < 16) {
                const int c0 = ct << 6;
                BufLoader bl{g_x2, H_};
                gemm_seg(acc, bl, Wmx2 + (size_t)c0 * H_, H_, As, Ws);
                store_tile(g_mx2, H_, c0, acc, nullptr);
            } else if (ct < 32) {
                const int c0 = (ct - 16) << 6;
                BufLoader bl{g_h2, H_};
                gemm_seg(acc, bl, Wmh2 + (size_t)c0 * H_, H_, As, Ws);
                store_tile(g_mh2, H_, c0, acc, nullptr);
            } else {
                const int c0 = (ct - 32) << 6;
                BufLoader bl{g_x2, H_};
                gemm_seg(acc, bl, Wih2 + (size_t)c0 * H_, H_, As, Ws);
                store_tile(g_z2, H4_, c0, acc, b2 + c0);
            }
        } else if (bid >= 96 && bid < 120) {
            const int p = bid - 96;
            u64 acc[4][4] = {};
            BufLoader bl{g_h1, H_};
            if (p < 8) {
                const int c0 = p << 6;
                gemm_seg(acc, bl, Wsh + (size_t)c0 * H_, H_, As, Ws);
                store_tile(g_zbb, MID_, c0, acc, nullptr);
            } else {
                const int c0 = (p - 8) << 6;
                gemm_seg(acc, bl, Wmh1 + (size_t)c0 * H_, H_, As, Ws);
                store_tile(g_mh, H_, c0, acc, nullptr);
            }
        }
        grid_barrier(gen);

        if (s0 > 0.5f) {
            // ---- P5: z2p[half] = (mx2*mh2)[:,koff:+512] @ Whh2[:,koff:+512]^T  (128 tasks, K=512)
            if (bid < 128) {
                const int r = bid;
                const int c0 = (r >> 1) << 6;
                const int koff = (r & 1) << 9;
                u64 acc[4][4] = {};
                MulLoader ml{g_mx2 + koff, g_mh2 + koff};
                gemm_seg(acc, ml, Whh2 + (size_t)c0 * H_ + koff, 512, As, Ws);
                store_tile((r & 1) ? g_z2p1 : g_z2p0, H4_, c0, acc, nullptr);
            }
            grid_barrier(gen);
        }

        // ---- P6: cell2 gates under scalar flag, write outs[:,t,:] + flags[t]
        // No trailing barrier: P6 writes {h2,c2,out}; next-step P2 touches disjoint buffers,
        // and the P2/P3-end barriers order P6 before any PHASE_A(t+1) read/write.
        if (bid < B_) {
            const int b = bid;
            const bool upd = s0 > 0.5f;
            const int j = tid << 2;
            const size_t o = (size_t)b * H_ + j;
            float4 h2v = *(const float4*)&g_h2[o];   // same-block r/w: L1 valid
            if (upd) {
                const size_t z = (size_t)b * H4_ + j;
                float4 zi = cg4(&g_z2[z]);            float4 pi0 = cg4(&g_z2p0[z]);            float4 pi1 = cg4(&g_z2p1[z]);
                float4 zf = cg4(&g_z2[z + H_]);       float4 pf0 = cg4(&g_z2p0[z + H_]);       float4 pf1 = cg4(&g_z2p1[z + H_]);
                float4 zg = cg4(&g_z2[z + 2 * H_]);   float4 pg0 = cg4(&g_z2p0[z + 2 * H_]);   float4 pg1 = cg4(&g_z2p1[z + 2 * H_]);
                float4 zo = cg4(&g_z2[z + 3 * H_]);   float4 po0 = cg4(&g_z2p0[z + 3 * H_]);   float4 po1 = cg4(&g_z2p1[z + 3 * H_]);
                float4 c2v = *(const float4*)&g_c2[o];
                float xi[4] = {zi.x + pi0.x + pi1.x, zi.y + pi0.y + pi1.y, zi.z + pi0.z + pi1.z, zi.w + pi0.w + pi1.w};
                float xf[4] = {zf.x + pf0.x + pf1.x, zf.y + pf0.y + pf1.y, zf.z + pf0.z + pf1.z, zf.w + pf0.w + pf1.w};
                float xg[4] = {zg.x + pg0.x + pg1.x, zg.y + pg0.y + pg1.y, zg.z + pg0.z + pg1.z, zg.w + pg0.w + pg1.w};
                float xo[4] = {zo.x + po0.x + po1.x, zo.y + po0.y + po1.y, zo.z + po0.z + po1.z, zo.w + po0.w + po1.w};
                float cv[4] = {c2v.x, c2v.y, c2v.z, c2v.w};
                float hn[4], cn[4];
#pragma unroll
                for (int q = 0; q < 4; q++) {
                    cn[q] = sigf(xf[q]) * cv[q] + sigf(xi[q]) * tanhf(xg[q]);
                    hn[q] = sigf(xo[q]) * tanhf(cn[q]);
                }
                h2v = make_float4(hn[0], hn[1], hn[2], hn[3]);
                *(float4*)&g_h2[o] = h2v;
                *(float4*)&g_c2[o] = make_float4(cn[0], cn[1], cn[2], cn[3]);
            }
            *(float4*)&out[(size_t)b * S_ * H_ + (size_t)t * H_ + j] = h2v;
            if (b == 0 && tid == 0 && out_flags) out_flags[t] = s0;
        }
    }

    // order all P6 writes before the cross-block final state copy
    grid_barrier(gen);
    if (out_h2) {
        for (int i = bid * NTHR + tid; i < B_ * H_; i += NBLK * NTHR) {
            out_h2[i] = cg1(&g_h2[i]);
            out_c2[i] = cg1(&g_c2[i]);
        }
    }
}

// ---------------- host: exactly ONE graph node ----------------
extern "C" void kernel_launch(void* const* d_in, const int* in_sizes, int n_in,
                              void* d_out, int out_size) {
    const int*   enc   = (const int*)d_in[0];
    const int*   encx  = (const int*)d_in[1];
    const float* we    = (const float*)d_in[2];
    const float* ee    = (const float*)d_in[3];
    const float* Wsi   = (const float*)d_in[4];
    const float* Wsh   = (const float*)d_in[5];
    const float* b_bd  = (const float*)d_in[6];
    const float* vs    = (const float*)d_in[7];
    const float* Wmx1  = (const float*)d_in[8];
    const float* Wmh1  = (const float*)d_in[9];
    const float* Wih1  = (const float*)d_in[10];
    const float* Whh1  = (const float*)d_in[11];
    const float* b1    = (const float*)d_in[12];
    const float* Wmx2  = (const float*)d_in[13];
    const float* Wmh2  = (const float*)d_in[14];
    const float* Wih2  = (const float*)d_in[15];
    const float* Whh2  = (const float*)d_in[16];
    const float* b2    = (const float*)d_in[17];
    float* out = (float*)d_out;

    const size_t outs_elems  = (size_t)B_ * S_ * H_;
    const size_t state_elems = (size_t)B_ * H_;
    float* out_h2 = nullptr;
    float* out_c2 = nullptr;
    float* out_flags = nullptr;
    if ((size_t)out_size >= outs_elems + 2 * state_elems + S_) {
        out_h2 = out + outs_elems;
        out_c2 = out_h2 + state_elems;
        out_flags = out_c2 + state_elems;
    }

    enc_kernel<<<NBLK, NTHR>>>(enc, encx, we, ee, Wsi, Wsh, b_bd, vs,
                               Wmx1, Wmh1, Wih1, Whh1, b1,
                               Wmx2, Wmh2, Wih2, Whh2, b2,
                               out, out_h2, out_c2, out_flags);
    (void)in_sizes; (void)n_in;
}

// round 12
// speedup vs baseline: 1.8310x; 1.2375x over previous
#include <cuda_runtime.h>
#include <cstdint>

#define B_    128
#define S_    512
#define H_    1024
#define MID_  512
#define E_    512
#define XE_   64
#define FEAT_ 576
#define H4_   4096
#define NBLK  296
#define NTHR  256

typedef unsigned long long u64;

// ---------------- persistent state + scratch (device globals; no allocs) ----------------
__device__ float g_h1[B_ * H_];
__device__ float g_c1[B_ * H_];
__device__ float g_h2[B_ * H_];
__device__ float g_c2[B_ * H_];
__device__ float g_zbb[B_ * MID_];
__device__ float g_mh[B_ * H_];
__device__ float g_z1p0[B_ * H4_];
__device__ float g_z1p1[B_ * H4_];
__device__ float g_x2[B_ * H_];
__device__ float g_mx2[B_ * H_];
__device__ float g_mh2[B_ * H_];
__device__ float g_z2[B_ * H4_];
__device__ float g_z2p0[B_ * H4_];
__device__ float g_z2p1[B_ * H4_];
__device__ float g_s[B_];
__device__ unsigned g_bar_count = 0;
__device__ unsigned g_bar_gen = 0;
// precomputed x-side results for ALL steps (input-only dependent)
__device__ float g_zba_all[S_ * B_ * MID_];   // 134 MB
__device__ float g_mx_all[S_ * B_ * H_];      // 268 MB
__device__ float g_z1_all[S_ * B_ * H4_];     // 1.07 GB

__device__ __forceinline__ float sigf(float x) { return 1.f / (1.f + expf(-x)); }
// L2-only loads for cross-block data (L1 persists within a persistent kernel -> stale otherwise)
__device__ __forceinline__ float4 cg4(const float* p) { return __ldcg((const float4*)p); }
__device__ __forceinline__ float  cg1(const float* p) { return __ldcg(p); }

// packed fp32x2 FMA (sm_100+): doubles fma-pipe flops per issue slot
#define FMA2(acc, a, b) asm("fma.rn.f32x2 %0, %1, %2, %0;" : "+l"(acc) : "l"(a), "l"(b))
#define PACK2(d, f)     asm("mov.b64 %0, {%1, %1};" : "=l"(d) : "r"(__float_as_uint(f)))
#define UNPACK2(lo, hi, v) asm("mov.b64 {%0, %1}, %2;" : "=r"(lo), "=r"(hi) : "l"(v))

// ---------------- grid-wide barrier (all NBLK blocks co-resident: 2 CTAs x 148 SMs) ----------------
__device__ __forceinline__ void grid_barrier(unsigned& gen) {
    __syncthreads();
    if (threadIdx.x == 0) {
        __threadfence();
        unsigned arrived = atomicAdd(&g_bar_count, 1u) + 1u;
        if (arrived == (unsigned)NBLK) {
            g_bar_count = 0;
            __threadfence();
            atomicExch(&g_bar_gen, gen + 1u);
        } else {
            unsigned cur;
            do {
                __nanosleep(64);
                asm volatile("ld.global.cg.u32 %0, [%1];" : "=r"(cur) : "l"(&g_bar_gen));
            } while (cur == gen);
        }
        __threadfence();
    }
    __syncthreads();
    gen++;
}

// ---------------- A-tile loaders (M = 128 = full batch) ----------------
struct BufLoader {
    const float* A; int lda;
    __device__ __forceinline__ float4 ld(int m, int k) const {
        return cg4(A + (size_t)m * lda + k);
    }
};
struct MulLoader {  // A[m][k] = X[m][k] * Y[m][k], both [*, H_] (pre-offset by koff)
    const float* X; const float* Y;
    __device__ __forceinline__ float4 ld(int m, int k) const {
        float4 a = cg4(X + (size_t)m * H_ + k);
        float4 b = cg4(Y + (size_t)m * H_ + k);
        return make_float4(a.x * b.x, a.y * b.y, a.z * b.z, a.w * b.w);
    }
};
struct EmbLoader {  // gathered embedding row: [word_emb | extra_emb] (read-only tables, L1 ok)
    const float* we; const float* ee; const int* sw; const int* se;
    __device__ __forceinline__ float4 ld(int m, int k) const {
        if (k < E_) return *(const float4*)(we + (size_t)sw[m] * E_ + k);
        return *(const float4*)(ee + (size_t)se[m] * XE_ + (k - E_));
    }
};

typedef float SmA[16][128];
typedef float SmW[16][64];

// ---------------- 128x64 tile GEMM: acc += A[128,K] @ W[64,K]^T ----------------
// EXACT R8 version (proven best): 256 threads, BK=16, 8 rows x 4 cols per thread
// via row-pair fp32x2, double-buffered smem, one-chunk global prefetch.
// Per-output k-order identical to the scalar loop -> bit-identical numerics.
template <class AL>
__device__ __forceinline__ void gemm_seg(u64 (&acc)[4][4], const AL& al,
                                         const float* __restrict__ W, int K,
                                         SmA* As, SmW* Ws) {
    const int tid = threadIdx.x;
    const int lm  = tid >> 2;          // 0..63 : load row (and +64)
    const int lk  = (tid & 3) << 2;    // 0,4,8,12 : load k offset
    const int tm  = tid >> 4;          // 0..15 : rows 8tm..8tm+7
    const int tn  = tid & 15;          // 0..15 : cols 4tn..4tn+3
    float4 a0 = al.ld(lm, lk);
    float4 a1 = al.ld(lm + 64, lk);
    float4 w  = *(const float4*)(W + (size_t)lm * K + lk);
    const int nch = K >> 4;
    int buf = 0;
    for (int ch = 0; ch < nch; ch++) {
        As[buf][lk + 0][lm] = a0.x; As[buf][lk + 1][lm] = a0.y;
        As[buf][lk + 2][lm] = a0.z; As[buf][lk + 3][lm] = a0.w;
        As[buf][lk + 0][lm + 64] = a1.x; As[buf][lk + 1][lm + 64] = a1.y;
        As[buf][lk + 2][lm + 64] = a1.z; As[buf][lk + 3][lm + 64] = a1.w;
        Ws[buf][lk + 0][lm] = w.x; Ws[buf][lk + 1][lm] = w.y;
        Ws[buf][lk + 2][lm] = w.z; Ws[buf][lk + 3][lm] = w.w;
        __syncthreads();
        if (ch + 1 < nch) {   // prefetch next chunk; hidden behind compute
            a0 = al.ld(lm, ((ch + 1) << 4) + lk);
            a1 = al.ld(lm + 64, ((ch + 1) << 4) + lk);
            w  = *(const float4*)(W + (size_t)lm * K + ((ch + 1) << 4) + lk);
        }
#pragma unroll
        for (int kk = 0; kk < 16; kk++) {
            ulonglong2 ar0 = *(const ulonglong2*)&As[buf][kk][tm << 3];        // rowpairs 0,1
            ulonglong2 ar1 = *(const ulonglong2*)&As[buf][kk][(tm << 3) + 4];  // rowpairs 2,3
            float4 wv = *(const float4*)&Ws[buf][kk][tn << 2];
            u64 wp;
            PACK2(wp, wv.x);
            FMA2(acc[0][0], ar0.x, wp); FMA2(acc[0][1], ar0.y, wp);
            FMA2(acc[0][2], ar1.x, wp); FMA2(acc[0][3], ar1.y, wp);
            PACK2(wp, wv.y);
            FMA2(acc[1][0], ar0.x, wp); FMA2(acc[1][1], ar0.y, wp);
            FMA2(acc[1][2], ar1.x, wp); FMA2(acc[1][3], ar1.y, wp);
            PACK2(wp, wv.z);
            FMA2(acc[2][0], ar0.x, wp); FMA2(acc[2][1], ar0.y, wp);
            FMA2(acc[2][2], ar1.x, wp); FMA2(acc[2][3], ar1.y, wp);
            PACK2(wp, wv.w);
            FMA2(acc[3][0], ar0.x, wp); FMA2(acc[3][1], ar0.y, wp);
            FMA2(acc[3][2], ar1.x, wp); FMA2(acc[3][3], ar1.y, wp);
        }
        buf ^= 1;
    }
    __syncthreads();   // protect smem before reuse by next task/phase
}

__device__ __forceinline__ void store_tile(float* __restrict__ C, int ldc, int c0,
                                           u64 (&acc)[4][4], const float* __restrict__ bias) {
    const int tid = threadIdx.x;
    const int tm = tid >> 4, tn = tid & 15;
    float4 bv = make_float4(0.f, 0.f, 0.f, 0.f);
    if (bias) bv = *(const float4*)(bias + (tn << 2));
#pragma unroll
    for (int rp = 0; rp < 4; rp++) {
        unsigned l0, h0, l1, h1, l2, h2, l3, h3;
        UNPACK2(l0, h0, acc[0][rp]);
        UNPACK2(l1, h1, acc[1][rp]);
        UNPACK2(l2, h2, acc[2][rp]);
        UNPACK2(l3, h3, acc[3][rp]);
        const int r0 = (tm << 3) + (rp << 1);
        *(float4*)(C + (size_t)r0 * ldc + c0 + (tn << 2)) =
            make_float4(__uint_as_float(l0) + bv.x, __uint_as_float(l1) + bv.y,
                        __uint_as_float(l2) + bv.z, __uint_as_float(l3) + bv.w);
        *(float4*)(C + (size_t)(r0 + 1) * ldc + c0 + (tn << 2)) =
            make_float4(__uint_as_float(h0) + bv.x, __uint_as_float(h1) + bv.y,
                        __uint_as_float(h2) + bv.z, __uint_as_float(h3) + bv.w);
    }
}

// ---------------- P6 body: cell2 gates (flag-gated) + write outs[:,t,:] ----------------
__device__ __forceinline__ void do_p6(int b, int t, float s_flag,
                                      float* __restrict__ out, float* __restrict__ out_flags) {
    const int tid = threadIdx.x;
    const bool upd = s_flag > 0.5f;
    const int j = tid << 2;
    const size_t o = (size_t)b * H_ + j;
    float4 h2v = *(const float4*)&g_h2[o];   // same-block r/w across steps: L1 valid
    if (upd) {
        const size_t z = (size_t)b * H4_ + j;
        float4 zi = cg4(&g_z2[z]);            float4 pi0 = cg4(&g_z2p0[z]);            float4 pi1 = cg4(&g_z2p1[z]);
        float4 zf = cg4(&g_z2[z + H_]);       float4 pf0 = cg4(&g_z2p0[z + H_]);       float4 pf1 = cg4(&g_z2p1[z + H_]);
        float4 zg = cg4(&g_z2[z + 2 * H_]);   float4 pg0 = cg4(&g_z2p0[z + 2 * H_]);   float4 pg1 = cg4(&g_z2p1[z + 2 * H_]);
        float4 zo = cg4(&g_z2[z + 3 * H_]);   float4 po0 = cg4(&g_z2p0[z + 3 * H_]);   float4 po1 = cg4(&g_z2p1[z + 3 * H_]);
        float4 c2v = *(const float4*)&g_c2[o];
        float xi[4] = {zi.x + pi0.x + pi1.x, zi.y + pi0.y + pi1.y, zi.z + pi0.z + pi1.z, zi.w + pi0.w + pi1.w};
        float xf[4] = {zf.x + pf0.x + pf1.x, zf.y + pf0.y + pf1.y, zf.z + pf0.z + pf1.z, zf.w + pf0.w + pf1.w};
        float xg[4] = {zg.x + pg0.x + pg1.x, zg.y + pg0.y + pg1.y, zg.z + pg0.z + pg1.z, zg.w + pg0.w + pg1.w};
        float xo[4] = {zo.x + po0.x + po1.x, zo.y + po0.y + po1.y, zo.z + po0.z + po1.z, zo.w + po0.w + po1.w};
        float cv[4] = {c2v.x, c2v.y, c2v.z, c2v.w};
        float hn[4], cn[4];
#pragma unroll
        for (int q = 0; q < 4; q++) {
            cn[q] = sigf(xf[q]) * cv[q] + sigf(xi[q]) * tanhf(xg[q]);
            hn[q] = sigf(xo[q]) * tanhf(cn[q]);
        }
        h2v = make_float4(hn[0], hn[1], hn[2], hn[3]);
        *(float4*)&g_h2[o] = h2v;
        *(float4*)&g_c2[o] = make_float4(cn[0], cn[1], cn[2], cn[3]);
    }
    *(float4*)&out[(size_t)b * S_ * H_ + (size_t)t * H_ + j] = h2v;
    if (b == 0 && tid == 0 && out_flags) out_flags[t] = s_flag;
}

// ---------------- the single persistent kernel ----------------
__global__ __launch_bounds__(NTHR, 2) void enc_kernel(
    const int* __restrict__ enc, const int* __restrict__ encx,
    const float* __restrict__ we, const float* __restrict__ ee,
    const float* __restrict__ Wsi, const float* __restrict__ Wsh,
    const float* __restrict__ b_bd, const float* __restrict__ vs,
    const float* __restrict__ Wmx1, const float* __restrict__ Wmh1,
    const float* __restrict__ Wih1, const float* __restrict__ Whh1, const float* __restrict__ b1,
    const float* __restrict__ Wmx2, const float* __restrict__ Wmh2,
    const float* __restrict__ Wih2, const float* __restrict__ Whh2, const float* __restrict__ b2,
    float* __restrict__ out, float* __restrict__ out_h2,
    float* __restrict__ out_c2, float* __restrict__ out_flags) {
    __shared__ float As[2][16][128];
    __shared__ float Ws[2][16][64];
    __shared__ float red[NTHR];
    __shared__ int sw[128], se[128];
    const int tid = threadIdx.x;
    const int bid = blockIdx.x;
    unsigned gen = *((volatile unsigned*)&g_bar_gen);  // persists across graph replays

    // init: zero recurrent state AND the h-side scratch for t=0 (h1=0 -> zbb=0, mh=0)
    for (int i = bid * NTHR + tid; i < B_ * H_; i += NBLK * NTHR) {
        g_h1[i] = 0.f; g_c1[i] = 0.f; g_h2[i] = 0.f; g_c2[i] = 0.f; g_mh[i] = 0.f;
    }
    for (int i = bid * NTHR + tid; i < B_ * MID_; i += NBLK * NTHR) g_zbb[i] = 0.f;

    // ---- PRECOMPUTE: all x-side GEMMs for every step (no recurrent dependency).
    //      88 tasks/step x 512 steps, perfectly parallel, 2 CTAs/SM -> 16 warps/SM.
    for (int task = bid; task < S_ * 88; task += NBLK) {
        const int t  = task / 88;
        const int ct = task - t * 88;
        if (tid < 128) {
            sw[tid] = enc[(size_t)tid * S_ + t];
            se[tid] = encx[(size_t)tid * S_ + t];
        }
        __syncthreads();
        u64 acc[4][4] = {};
        EmbLoader el{we, ee, sw, se};
        if (ct < 8) {
            const int c0 = ct << 6;
            gemm_seg(acc, el, Wsi + (size_t)c0 * FEAT_, FEAT_, As, Ws);
            store_tile(g_zba_all + (size_t)t * B_ * MID_, MID_, c0, acc, b_bd + c0);
        } else if (ct < 24) {
            const int c0 = (ct - 8) << 6;
            gemm_seg(acc, el, Wmx1 + (size_t)c0 * FEAT_, FEAT_, As, Ws);
            store_tile(g_mx_all + (size_t)t * B_ * H_, H_, c0, acc, nullptr);
        } else {
            const int c0 = (ct - 24) << 6;
            gemm_seg(acc, el, Wih1 + (size_t)c0 * FEAT_, FEAT_, As, Ws);
            store_tile(g_z1_all + (size_t)t * B_ * H4_, H4_, c0, acc, b1 + c0);
        }
    }
    grid_barrier(gen);

    float s_prev = 0.f;   // flag of step t-1 (uniform across blocks)

    for (int t = 0; t < S_; t++) {
        // ---- PHASE_BC: P2(t) on blocks 0..127 || P5(t-1) on blocks 168..295 (if prev flag).
        //      Second-CTA placement -> both share SMs with 16 warps; one overlapped wave.
        if (bid < 128) {
            const int r = bid;
            const int c0 = (r >> 1) << 6;
            const int koff = (r & 1) << 9;
            u64 acc[4][4] = {};
            MulLoader ml{g_mx_all + (size_t)t * B_ * H_ + koff, g_mh + koff};
            gemm_seg(acc, ml, Whh1 + (size_t)c0 * H_ + koff, 512, As, Ws);
            store_tile((r & 1) ? g_z1p1 : g_z1p0, H4_, c0, acc, nullptr);
        } else if (bid >= 168 && t > 0 && s_prev > 0.5f) {
            const int r = bid - 168;
            const int c0 = (r >> 1) << 6;
            const int koff = (r & 1) << 9;
            u64 acc[4][4] = {};
            MulLoader ml{g_mx2 + koff, g_mh2 + koff};
            gemm_seg(acc, ml, Whh2 + (size_t)c0 * H_ + koff, 512, As, Ws);
            store_tile((r & 1) ? g_z2p1 : g_z2p0, H4_, c0, acc, nullptr);
        }
        grid_barrier(gen);

        // ---- PHASE_CD: P3(t) on blocks 0..127 || P6(t-1) on blocks 168..295.
        if (bid < B_) {
            const int b = bid;
            const float* zba = g_zba_all + (size_t)t * B_ * MID_;
            float v = (cg1(&zba[(size_t)b * MID_ + tid]) + cg1(&g_zbb[(size_t)b * MID_ + tid])) * vs[tid] +
                      (cg1(&zba[(size_t)b * MID_ + 256 + tid]) + cg1(&g_zbb[(size_t)b * MID_ + 256 + tid])) * vs[256 + tid];
            red[tid] = v;
            __syncthreads();
            for (int off = 128; off > 0; off >>= 1) {
                if (tid < off) red[tid] += red[tid + off];
                __syncthreads();
            }
            const float s = (red[0] > 0.f) ? 1.f : 0.f;  // sigmoid(x)>0.5 <=> x>0 (exact)
            if (tid == 0) g_s[b] = s;
            {
                const int j = tid << 2;   // 256 threads x float4 == H_
                const size_t o = (size_t)b * H_ + j;
                const float* z1 = g_z1_all + (size_t)t * B_ * H4_;
                const size_t z = (size_t)b * H4_ + j;
                float4 zi = cg4(&z1[z]);            float4 pi0 = cg4(&g_z1p0[z]);            float4 pi1 = cg4(&g_z1p1[z]);
                float4 zf = cg4(&z1[z + H_]);       float4 pf0 = cg4(&g_z1p0[z + H_]);       float4 pf1 = cg4(&g_z1p1[z + H_]);
                float4 zg = cg4(&z1[z + 2 * H_]);   float4 pg0 = cg4(&g_z1p0[z + 2 * H_]);   float4 pg1 = cg4(&g_z1p1[z + 2 * H_]);
                float4 zo = cg4(&z1[z + 3 * H_]);   float4 po0 = cg4(&g_z1p0[z + 3 * H_]);   float4 po1 = cg4(&g_z1p1[z + 3 * H_]);
                float4 c1v = *(const float4*)&g_c1[o];   // same-block r/w across steps: L1 valid
                float xi[4] = {zi.x + pi0.x + pi1.x, zi.y + pi0.y + pi1.y, zi.z + pi0.z + pi1.z, zi.w + pi0.w + pi1.w};
                float xf[4] = {zf.x + pf0.x + pf1.x, zf.y + pf0.y + pf1.y, zf.z + pf0.z + pf1.z, zf.w + pf0.w + pf1.w};
                float xg[4] = {zg.x + pg0.x + pg1.x, zg.y + pg0.y + pg1.y, zg.z + pg0.z + pg1.z, zg.w + pg0.w + pg1.w};
                float xo[4] = {zo.x + po0.x + po1.x, zo.y + po0.y + po1.y, zo.z + po0.z + po1.z, zo.w + po0.w + po1.w};
                float cv[4] = {c1v.x, c1v.y, c1v.z, c1v.w};
                float x2v[4], h1v[4], c1n[4];
#pragma unroll
                for (int q = 0; q < 4; q++) {
                    float cn = sigf(xf[q]) * cv[q] + sigf(xi[q]) * tanhf(xg[q]);
                    float hn = sigf(xo[q]) * tanhf(cn);
                    x2v[q] = hn * s;
                    h1v[q] = hn * (1.f - s);
                    c1n[q] = cn * (1.f - s);
                }
                *(float4*)&g_x2[o] = make_float4(x2v[0], x2v[1], x2v[2], x2v[3]);
                *(float4*)&g_h1[o] = make_float4(h1v[0], h1v[1], h1v[2], h1v[3]);
                *(float4*)&g_c1[o] = make_float4(c1n[0], c1n[1], c1n[2], c1n[3]);
            }
        } else if (bid >= 168 && t > 0) {
            do_p6(bid - 168, t - 1, s_prev, out, out_flags);
        }
        grid_barrier(gen);

        const float s_cur = cg1(&g_s[0]);  // uniform after barrier -> uniform control flow

        // ---- PHASE_A: blocks 0..95: P4(t) when flag; blocks 96..119: P1'(t+1) = zbb/mh.
        if (s_cur > 0.5f && bid < 96) {
            const int ct = bid;
            u64 acc[4][4] = {};
            if (ct < 16) {
                const int c0 = ct << 6;
                BufLoader bl{g_x2, H_};
                gemm_seg(acc, bl, Wmx2 + (size_t)c0 * H_, H_, As, Ws);
                store_tile(g_mx2, H_, c0, acc, nullptr);
            } else if (ct < 32) {
                const int c0 = (ct - 16) << 6;
                BufLoader bl{g_h2, H_};
                gemm_seg(acc, bl, Wmh2 + (size_t)c0 * H_, H_, As, Ws);
                store_tile(g_mh2, H_, c0, acc, nullptr);
            } else {
                const int c0 = (ct - 32) << 6;
                BufLoader bl{g_x2, H_};
                gemm_seg(acc, bl, Wih2 + (size_t)c0 * H_, H_, As, Ws);
                store_tile(g_z2, H4_, c0, acc, b2 + c0);
            }
        } else if (bid >= 96 && bid < 120) {
            const int p = bid - 96;
            u64 acc[4][4] = {};
            BufLoader bl{g_h1, H_};
            if (p < 8) {
                const int c0 = p << 6;
                gemm_seg(acc, bl, Wsh + (size_t)c0 * H_, H_, As, Ws);
                store_tile(g_zbb, MID_, c0, acc, nullptr);
            } else {
                const int c0 = (p - 8) << 6;
                gemm_seg(acc, bl, Wmh1 + (size_t)c0 * H_, H_, As, Ws);
                store_tile(g_mh, H_, c0, acc, nullptr);
            }
        }
        grid_barrier(gen);

        s_prev = s_cur;
    }

    // ---- epilogue: P5(S-1) if flagged, then P6(S-1), then final state copy.
    if (s_prev > 0.5f) {
        if (bid < 128) {
            const int r = bid;
            const int c0 = (r >> 1) << 6;
            const int koff = (r & 1) << 9;
            u64 acc[4][4] = {};
            MulLoader ml{g_mx2 + koff, g_mh2 + koff};
            gemm_seg(acc, ml, Whh2 + (size_t)c0 * H_ + koff, 512, As, Ws);
            store_tile((r & 1) ? g_z2p1 : g_z2p0, H4_, c0, acc, nullptr);
        }
        grid_barrier(gen);
    }
    if (bid >= 168) {
        do_p6(bid - 168, S_ - 1, s_prev, out, out_flags);
    }
    grid_barrier(gen);
    if (out_h2) {
        for (int i = bid * NTHR + tid; i < B_ * H_; i += NBLK * NTHR) {
            out_h2[i] = cg1(&g_h2[i]);
            out_c2[i] = cg1(&g_c2[i]);
        }
    }
}

// ---------------- host: exactly ONE graph node ----------------
extern "C" void kernel_launch(void* const* d_in, const int* in_sizes, int n_in,
                              void* d_out, int out_size) {
    const int*   enc   = (const int*)d_in[0];
    const int*   encx  = (const int*)d_in[1];
    const float* we    = (const float*)d_in[2];
    const float* ee    = (const float*)d_in[3];
    const float* Wsi   = (const float*)d_in[4];
    const float* Wsh   = (const float*)d_in[5];
    const float* b_bd  = (const float*)d_in[6];
    const float* vs    = (const float*)d_in[7];
    const float* Wmx1  = (const float*)d_in[8];
    const float* Wmh1  = (const float*)d_in[9];
    const float* Wih1  = (const float*)d_in[10];
    const float* Whh1  = (const float*)d_in[11];
    const float* b1    = (const float*)d_in[12];
    const float* Wmx2  = (const float*)d_in[13];
    const float* Wmh2  = (const float*)d_in[14];
    const float* Wih2  = (const float*)d_in[15];
    const float* Whh2  = (const float*)d_in[16];
    const float* b2    = (const float*)d_in[17];
    float* out = (float*)d_out;

    const size_t outs_elems  = (size_t)B_ * S_ * H_;
    const size_t state_elems = (size_t)B_ * H_;
    float* out_h2 = nullptr;
    float* out_c2 = nullptr;
    float* out_flags = nullptr;
    if ((size_t)out_size >= outs_elems + 2 * state_elems + S_) {
        out_h2 = out + outs_elems;
        out_c2 = out_h2 + state_elems;
        out_flags = out_c2 + state_elems;
    }

    enc_kernel<<<NBLK, NTHR>>>(enc, encx, we, ee, Wsi, Wsh, b_bd, vs,
                               Wmx1, Wmh1, Wih1, Whh1, b1,
                               Wmx2, Wmh2, Wih2, Whh2, b2,
                               out, out_h2, out_c2, out_flags);
    (void)in_sizes; (void)n_in;
}